// round 5
// baseline (speedup 1.0000x reference)
#include <cuda_runtime.h>
#include <math.h>

// Problem constants
#define T_STEPS 1024
#define D_IN    2048
#define NH      2048
#define CATS    1000

// Recurrence kernel config
#define NBLK    128          // persistent blocks (1 block/SM)
#define NTH     512          // 16 warps
#define HPB     16           // hidden indices owned per block (z AND ht)
#define NSTAGE  27           // rows of U pinned in SMEM per block (of 32)
// smem: U rows + p (block-local, persistent) + partials
#define SMEM_FLOATS (NSTAGE*NH + NH + 64)
#define SMEM_BYTES  (SMEM_FLOATS * 4)

// Scratch (device globals; no allocation allowed)
__device__ float g_XZ[T_STEPS * NH];
__device__ float g_XH[T_STEPS * NH];
__device__ float g_Zb[4][NH];      // gate z, 4-deep ring by generation&3
__device__ float g_HTb[4][NH];     // gate htilde
__device__ float g_LOGITS[1024];
// Split-phase barrier state. Each array is 256B -> distinct L2 lines, so
// gen polls never contend with count atomics.
__device__ unsigned int g_cntA[64];
__device__ unsigned int g_genA[64];
__device__ unsigned int g_cntB[64];
__device__ unsigned int g_genB[64];

// ---------------------------------------------------------------------------
// GEMM: C[t, n] = sum_k x[t,k] * W[n,k]; n<2048 -> Wz -> XZ, else Wh -> XH.
// ---------------------------------------------------------------------------
#define GBM 128
#define GBN 64
#define GBK 16

__global__ __launch_bounds__(256) void gemm_xproj(
    const float* __restrict__ x,
    const float* __restrict__ Wz,
    const float* __restrict__ Wh)
{
    __shared__ float As[GBK][GBM + 2];
    __shared__ float Bs[GBK][GBN + 2];

    const int tid  = threadIdx.x;
    const int row0 = blockIdx.y * GBM;
    const int col0 = blockIdx.x * GBN;

    const float* Bbase = (col0 < NH) ? (Wz + (size_t)col0 * D_IN)
                                     : (Wh + (size_t)(col0 - NH) * D_IN);

    const int trow = tid >> 4;
    const int tcol = tid & 15;
    const int m0 = trow * 8;
    const int n0 = tcol * 4;

    float acc[8][4];
    #pragma unroll
    for (int i = 0; i < 8; i++)
        #pragma unroll
        for (int j = 0; j < 4; j++) acc[i][j] = 0.f;

    for (int kt = 0; kt < D_IN; kt += GBK) {
        #pragma unroll
        for (int u = 0; u < 2; u++) {
            int idx = tid + u * 256;
            int ar  = idx >> 2;
            int ac4 = idx & 3;
            float4 v = *(const float4*)(x + (size_t)(row0 + ar) * D_IN + kt + ac4 * 4);
            As[ac4 * 4 + 0][ar] = v.x;
            As[ac4 * 4 + 1][ar] = v.y;
            As[ac4 * 4 + 2][ar] = v.z;
            As[ac4 * 4 + 3][ar] = v.w;
        }
        {
            int br  = tid >> 2;
            int bc4 = tid & 3;
            float4 v = *(const float4*)(Bbase + (size_t)br * D_IN + kt + bc4 * 4);
            Bs[bc4 * 4 + 0][br] = v.x;
            Bs[bc4 * 4 + 1][br] = v.y;
            Bs[bc4 * 4 + 2][br] = v.z;
            Bs[bc4 * 4 + 3][br] = v.w;
        }
        __syncthreads();

        #pragma unroll
        for (int k = 0; k < GBK; k++) {
            float a[8], bb[4];
            #pragma unroll
            for (int i = 0; i < 8; i++) a[i] = As[k][m0 + i];
            #pragma unroll
            for (int j = 0; j < 4; j++) bb[j] = Bs[k][n0 + j];
            #pragma unroll
            for (int i = 0; i < 8; i++)
                #pragma unroll
                for (int j = 0; j < 4; j++) acc[i][j] += a[i] * bb[j];
        }
        __syncthreads();
    }

    #pragma unroll
    for (int i = 0; i < 8; i++) {
        int t = row0 + m0 + i;
        #pragma unroll
        for (int j = 0; j < 4; j++) {
            int n = col0 + n0 + j;
            if (n < NH) g_XZ[(size_t)t * NH + n] = acc[i][j];
            else        g_XH[(size_t)t * NH + (n - NH)] = acc[i][j];
        }
    }
}

// ---------------------------------------------------------------------------
// Split-phase barrier primitives (release/acquire; counts self-reset;
// gens monotonic and compared against a launch-start base, wrap-safe).
// ---------------------------------------------------------------------------
__device__ __forceinline__ void bar_arrive(unsigned int* cnt, unsigned int* gen)
{
    unsigned int old;
    asm volatile("atom.release.gpu.global.add.u32 %0, [%1], 1;"
                 : "=r"(old) : "l"(cnt));
    if (old == NBLK - 1) {
        unsigned int g;
        asm volatile("ld.relaxed.gpu.global.u32 %0, [%1];" : "=r"(g) : "l"(gen));
        asm volatile("st.relaxed.gpu.global.u32 [%0], %1;" :: "l"(cnt), "r"(0u));
        asm volatile("st.release.gpu.global.u32 [%0], %1;" :: "l"(gen), "r"(g + 1u));
    }
}

__device__ __forceinline__ void bar_wait(unsigned int* gen, unsigned int target)
{
    unsigned int v;
    do {
        asm volatile("ld.acquire.gpu.global.u32 %0, [%1];" : "=r"(v) : "l"(gen));
    } while ((int)(v - target) < 0);
}

// ---------------------------------------------------------------------------
// Persistent recurrence. Block b owns hidden indices [16b,16b+16).
// p is BLOCK-LOCAL smem, rolled redundantly by every block; only the gates
// (z, ht) are exchanged. Two timesteps per superstep, with SPLIT-PHASE
// barriers: waitA before roll A, waitB only after matvec A, so straggler
// matvec-B work overlaps other blocks' matvec A of the next superstep.
// ---------------------------------------------------------------------------
__global__ __launch_bounds__(NTH, 1) void gru_recurrence(
    const float* __restrict__ Uz, const float* __restrict__ Uh,
    const float* __restrict__ bz,
    const float* __restrict__ Wout,
    const float* __restrict__ zt0, const float* __restrict__ htilde0,
    const float* __restrict__ hprev0,
    float* __restrict__ out)
{
    extern __shared__ float sm[];
    float* smU   = sm;                   // NSTAGE * NH
    float* ps    = sm + NSTAGE * NH;     // NH : persistent local copy of p
    float* part0 = ps + NH;              // 32 partials, K-half 0
    float* part1 = part0 + 32;           // 32 partials, K-half 1

    const int tid  = threadIdx.x;
    const int w    = tid >> 5;
    const int lane = tid & 31;
    const int wp   = w & 7;              // row-group id
    const int kh   = w >> 3;             // K half
    const int b    = blockIdx.x;
    const int I0   = b * HPB;

    // Launch-start generation bases (stable: no concurrent updates yet).
    unsigned int baseA = 0, baseB = 0;
    if (tid == 0) {
        asm volatile("ld.relaxed.gpu.global.u32 %0, [%1];" : "=r"(baseA) : "l"(g_genA));
        asm volatile("ld.relaxed.gpu.global.u32 %0, [%1];" : "=r"(baseB) : "l"(g_genB));
    }

    // Pin NSTAGE matvec rows into SMEM. Row s: s<16 -> Uz[I0+s], else Uh[I0+s-16].
    for (int s = 0; s < NSTAGE; s++) {
        const float* src = (s < 16) ? (Uz + (size_t)(I0 + s) * NH)
                                    : (Uh + (size_t)(I0 + s - 16) * NH);
        for (int i = tid; i < NH / 4; i += NTH)
            ((float4*)(smU + (size_t)s * NH))[i] = ((const float4*)src)[i];
    }
    // p_0 = hprev0 (block-local full copy)
    float4* ps4 = (float4*)ps;
    ps4[tid] = ((const float4*)hprev0)[tid];

    const float bzv = (lane < 16) ? __ldg(bz + I0 + lane) : 0.f;

    // Per-warp row pointers (K-half slice)
    const int s3 = wp + 24;                       // only it=3 can be residual
    const bool resid = (s3 >= NSTAGE);
    const float4* r0 = (const float4*)(smU + (size_t)(wp)      * NH + kh * 1024);
    const float4* r1 = (const float4*)(smU + (size_t)(wp + 8)  * NH + kh * 1024);
    const float4* r2 = (const float4*)(smU + (size_t)(wp + 16) * NH + kh * 1024);
    const float4* r3s = resid
        ? (const float4*)(Uh + (size_t)(I0 + s3 - 16) * NH + kh * 1024)
        : (const float4*)(smU + (size_t)s3 * NH + kh * 1024);

    __syncthreads();

    // ---- matvec over current smem p, producing gate generation -> buf ----
    auto matvec_gates = [&](int buf, float xv) {
        float4 upre[8];
        if (resid) {
            #pragma unroll
            for (int j = 0; j < 8; j++) upre[j] = __ldg(r3s + j * 32 + lane);
        }
        float4 preg[8];
        #pragma unroll
        for (int j = 0; j < 8; j++) preg[j] = ps4[kh * 256 + j * 32 + lane];

        float a0 = 0.f, a1 = 0.f, a2 = 0.f, a3 = 0.f;
        #pragma unroll
        for (int j = 0; j < 8; j++) {
            float4 p = preg[j];
            float4 u;
            u = r0[j * 32 + lane];
            a0 += u.x * p.x + u.y * p.y + u.z * p.z + u.w * p.w;
            u = r1[j * 32 + lane];
            a1 += u.x * p.x + u.y * p.y + u.z * p.z + u.w * p.w;
            u = r2[j * 32 + lane];
            a2 += u.x * p.x + u.y * p.y + u.z * p.z + u.w * p.w;
            u = resid ? upre[j] : r3s[j * 32 + lane];
            a3 += u.x * p.x + u.y * p.y + u.z * p.z + u.w * p.w;
        }
        #pragma unroll
        for (int off = 16; off; off >>= 1) {
            a0 += __shfl_xor_sync(0xffffffffu, a0, off);
            a1 += __shfl_xor_sync(0xffffffffu, a1, off);
            a2 += __shfl_xor_sync(0xffffffffu, a2, off);
            a3 += __shfl_xor_sync(0xffffffffu, a3, off);
        }
        if (lane == 0) {
            float* pt = kh ? part1 : part0;
            pt[wp]      = a0;
            pt[wp + 8]  = a1;
            pt[wp + 16] = a2;
            pt[wp + 24] = a3;
        }
        __syncthreads();
        if (tid < 32) {
            float v = part0[tid] + part1[tid];
            if (tid < 16) {
                float pre = xv + v + bzv;
                g_Zb[buf][I0 + tid] = 1.f / (1.f + expf(-pre));
            } else {
                g_HTb[buf][I0 + tid - 16] = tanhf(xv + v);
            }
        }
    };

    // ---- supersteps: 2 timesteps per A/B barrier pair ----
    for (int m = 0; m < T_STEPS / 2; m++) {
        const int t = 2 * m;

        // x projections for both matvecs (gate warp only; independent of gates)
        float xv0 = 0.f, xv1 = 0.f;
        if (tid < 32) {
            if (tid < 16) {
                xv0 = __ldg(&g_XZ[(size_t)t * NH + I0 + tid]);
                xv1 = __ldg(&g_XZ[(size_t)(t + 1) * NH + I0 + tid]);
            } else {
                xv0 = __ldg(&g_XH[(size_t)t * NH + I0 + tid - 16]);
                xv1 = __ldg(&g_XH[(size_t)(t + 1) * NH + I0 + tid - 16]);
            }
        }

        // Roll A: p_t = (1-z_{t-1})*p_{t-1} + z_{t-1}*ht_{t-1}  (skip at m=0)
        if (m > 0) {
            if (tid == 0) bar_wait(g_genA, baseA + m);   // all G(2m-1) published
            __syncthreads();
            const int bA = (t - 1) & 3;
            float4 zA = __ldcg((const float4*)g_Zb[bA]  + tid);
            float4 hA = __ldcg((const float4*)g_HTb[bA] + tid);
            float4 p = ps4[tid];
            p.x = (1.f - zA.x) * p.x + zA.x * hA.x;
            p.y = (1.f - zA.y) * p.y + zA.y * hA.y;
            p.z = (1.f - zA.z) * p.z + zA.z * hA.z;
            p.w = (1.f - zA.w) * p.w + zA.w * hA.w;
            ps4[tid] = p;
            __syncthreads();
        }

        // Matvec over p_t -> gates G(2m+1); publish + arriveA
        matvec_gates((t + 1) & 3, xv0);
        if (tid < 32) {
            __syncwarp();
            if (tid == 0) bar_arrive(g_cntA, g_genA);
        }

        // waitB (usually already satisfied; overlaps stragglers' matvec B)
        if (m > 0) {
            if (tid == 0) bar_wait(g_genB, baseB + m);
        }
        __syncthreads();

        // Roll B: p_{t+1} = (1-z_t)*p_t + z_t*ht_t
        {
            float4 zB, hB;
            if (m > 0) {
                const int bB = t & 3;
                zB = __ldcg((const float4*)g_Zb[bB]  + tid);
                hB = __ldcg((const float4*)g_HTb[bB] + tid);
            } else {
                zB = ((const float4*)zt0)[tid];
                hB = ((const float4*)htilde0)[tid];
            }
            float4 p = ps4[tid];
            p.x = (1.f - zB.x) * p.x + zB.x * hB.x;
            p.y = (1.f - zB.y) * p.y + zB.y * hB.y;
            p.z = (1.f - zB.z) * p.z + zB.z * hB.z;
            p.w = (1.f - zB.w) * p.w + zB.w * hB.w;
            ps4[tid] = p;
        }
        __syncthreads();

        // Matvec over p_{t+1} -> gates G(2m+2); publish + arriveB
        matvec_gates((t + 2) & 3, xv1);
        if (tid < 32) {
            __syncwarp();
            if (tid == 0) bar_arrive(g_cntB, g_genB);
        }
    }

    // Final roll: p_1024 uses G(1023), published by superstep 511's matvec A.
    if (tid == 0) bar_wait(g_genA, baseA + T_STEPS / 2);
    __syncthreads();
    {
        const int bF = (T_STEPS - 1) & 3;
        float4 z = __ldcg((const float4*)g_Zb[bF]  + tid);
        float4 h = __ldcg((const float4*)g_HTb[bF] + tid);
        float4 p = ps4[tid];
        p.x = (1.f - z.x) * p.x + z.x * h.x;
        p.y = (1.f - z.y) * p.y + z.y * h.y;
        p.z = (1.f - z.z) * p.z + z.z * h.z;
        p.w = (1.f - z.w) * p.w + z.w * h.w;
        ps4[tid] = p;
    }
    __syncthreads();

    // Logits: warp gw = b*16 + w covers 1000 rows (p from local smem)
    {
        int gw = b * 16 + w;
        if (gw < CATS) {
            const float4* u4 = (const float4*)(Wout + (size_t)gw * NH);
            float acc = 0.f;
            #pragma unroll
            for (int j = 0; j < 16; j++) {
                float4 u = __ldg(u4 + j * 32 + lane);
                float4 p = ps4[j * 32 + lane];
                acc += u.x * p.x + u.y * p.y + u.z * p.z + u.w * p.w;
            }
            #pragma unroll
            for (int off = 16; off; off >>= 1)
                acc += __shfl_xor_sync(0xffffffffu, acc, off);
            if (lane == 0) g_LOGITS[gw] = acc;
        }
    }
    __syncthreads();                    // logits STGs ordered before arrive
    if (tid == 0) bar_arrive(g_cntA, g_genA);

    // Softmax in block 0 (reduction buffer reuses ps)
    if (b == 0) {
        if (tid == 0) bar_wait(g_genA, baseA + T_STEPS / 2 + 1);
        __syncthreads();
        float* red = ps;
        float lm = -1e30f;
        for (int c = tid; c < CATS; c += NTH) lm = fmaxf(lm, __ldcg(&g_LOGITS[c]));
        __syncthreads();
        red[tid] = lm; __syncthreads();
        for (int o = NTH / 2; o; o >>= 1) {
            if (tid < o) red[tid] = fmaxf(red[tid], red[tid + o]);
            __syncthreads();
        }
        float mx = red[0]; __syncthreads();
        float ls = 0.f;
        for (int c = tid; c < CATS; c += NTH) ls += expf(__ldcg(&g_LOGITS[c]) - mx);
        red[tid] = ls; __syncthreads();
        for (int o = NTH / 2; o; o >>= 1) {
            if (tid < o) red[tid] += red[tid + o];
            __syncthreads();
        }
        float inv = 1.f / red[0];
        for (int c = tid; c < CATS; c += NTH)
            out[c] = expf(__ldcg(&g_LOGITS[c]) - mx) * inv;
    }
}

// ---------------------------------------------------------------------------
extern "C" void kernel_launch(void* const* d_in, const int* in_sizes, int n_in,
                              void* d_out, int out_size)
{
    const float* x       = (const float*)d_in[0];
    const float* Wh      = (const float*)d_in[1];
    const float* Wz      = (const float*)d_in[2];
    // d_in[3] = Wr, d_in[7] = Ur, d_in[8] = br: dead code in reference
    const float* Uh      = (const float*)d_in[4];
    const float* Uz      = (const float*)d_in[5];
    const float* bz      = (const float*)d_in[6];
    const float* Wout    = (const float*)d_in[9];
    // d_in[10] = h0: never read by the reference recurrence
    const float* zt0     = (const float*)d_in[11];
    const float* htilde0 = (const float*)d_in[12];
    const float* hprev0  = (const float*)d_in[13];
    float* out = (float*)d_out;

    dim3 ggrid((NH * 2) / GBN, T_STEPS / GBM);
    gemm_xproj<<<ggrid, 256>>>(x, Wz, Wh);

    cudaFuncSetAttribute(gru_recurrence,
                         cudaFuncAttributeMaxDynamicSharedMemorySize, SMEM_BYTES);
    gru_recurrence<<<NBLK, NTH, SMEM_BYTES>>>(Uz, Uh, bz, Wout,
                                              zt0, htilde0, hprev0, out);
}